// round 17
// baseline (speedup 1.0000x reference)
#include <cuda_runtime.h>
#include <cuda_bf16.h>

// NuclearLossFunc: loss = sum(x^2) / (B*C), x: (32,64,256,256) fp32
// = 134,217,728 elements = 512 MiB read. Pure HBM-bound reduction.
//
// R17: champion config (592x512 single wave, 32 regs, fused last-block
// finalize — triple-confirmed 82.0-82.4us) with exactly ONE change:
// loads carry the L2::256B promotion hint (ld.global.nc.L2::256B),
// pairing adjacent sectors into 256B DRAM fetches to trim row-activate
// overhead on the sequential stream. Same register footprint as the
// compiler's LDG.128.NC (4 output regs); structure untouched.
// Deterministic: fixed trees, final accumulate in double.

#define NBLOCKS  592            // 148 SMs * 4 CTAs -> exactly one wave
#define NTHREADS 512

__device__ float        g_partials[NBLOCKS];
__device__ unsigned int g_count;   // zero-initialized at module load

__device__ __forceinline__ float4 ldg_256b(const float4* p) {
    float4 v;
    asm volatile("ld.global.nc.L2::256B.v4.f32 {%0,%1,%2,%3}, [%4];"
                 : "=f"(v.x), "=f"(v.y), "=f"(v.z), "=f"(v.w)
                 : "l"(p));
    return v;
}

__global__ __launch_bounds__(NTHREADS) void sqsum_fused_kernel(
    const float4* __restrict__ in, long long n4,
    float* __restrict__ out, float scale)
{
    const int lane = threadIdx.x & 31;
    const int wid  = threadIdx.x >> 5;
    __shared__ float ws[NTHREADS / 32];
    __shared__ bool  s_is_last;

    // ---- hot loop: champion structure, L2::256B-hinted loads ----
    float s0 = 0.f, s1 = 0.f, s2 = 0.f, s3 = 0.f;
    long long idx    = (long long)blockIdx.x * blockDim.x + threadIdx.x;
    long long stride = (long long)gridDim.x * blockDim.x;

    for (long long i = idx; i < n4; i += stride) {
        float4 v = ldg_256b(in + i);
        s0 = fmaf(v.x, v.x, s0);
        s1 = fmaf(v.y, v.y, s1);
        s2 = fmaf(v.z, v.z, s2);
        s3 = fmaf(v.w, v.w, s3);
    }
    float s = (s0 + s1) + (s2 + s3);

    #pragma unroll
    for (int o = 16; o > 0; o >>= 1)
        s += __shfl_xor_sync(0xffffffffu, s, o);

    if (lane == 0) ws[wid] = s;
    __syncthreads();

    if (wid == 0) {
        s = (lane < NTHREADS / 32) ? ws[lane] : 0.f;
        #pragma unroll
        for (int o = 16; o > 0; o >>= 1)
            s += __shfl_xor_sync(0xffffffffu, s, o);
        if (lane == 0) g_partials[blockIdx.x] = s;   // released by atomic below
    }

    // ---- last-block election: one acq_rel atomic, no fence ----
    if (threadIdx.x == 0) {
        unsigned int ticket;
        asm volatile("atom.add.acq_rel.gpu.u32 %0, [%1], 1;"
                     : "=r"(ticket) : "l"(&g_count) : "memory");
        s_is_last = (ticket == (unsigned int)(gridDim.x - 1));
    }
    __syncthreads();
    if (!s_is_last) return;

    // ---- last block: reduce 592 partials in double (deterministic) ----
    __shared__ double wd[NTHREADS / 32];
    double d = 0.0;
    for (int p = threadIdx.x; p < NBLOCKS; p += NTHREADS)
        d += (double)g_partials[p];

    #pragma unroll
    for (int o = 16; o > 0; o >>= 1)
        d += __shfl_xor_sync(0xffffffffu, d, o);

    if (lane == 0) wd[wid] = d;
    __syncthreads();

    if (wid == 0) {
        d = (lane < NTHREADS / 32) ? wd[lane] : 0.0;
        #pragma unroll
        for (int o = 16; o > 0; o >>= 1)
            d += __shfl_xor_sync(0xffffffffu, d, o);
        if (lane == 0) {
            out[0] = (float)(d * (double)scale);
            g_count = 0;  // reset for graph replay
        }
    }
}

extern "C" void kernel_launch(void* const* d_in, const int* in_sizes, int n_in,
                              void* d_out, int out_size)
{
    const float* x = (const float*)d_in[0];
    long long n = (long long)in_sizes[0];     // 134217728, divisible by 4
    long long n4 = n >> 2;

    // B*C = n / (256*256) = 2048
    float scale = 1.0f / (float)(n / (256LL * 256LL));

    sqsum_fused_kernel<<<NBLOCKS, NTHREADS>>>((const float4*)x, n4,
                                              (float*)d_out, scale);
}